// round 16
// baseline (speedup 1.0000x reference)
#include <cuda_runtime.h>
#include <cstdint>
#include <math.h>

#define BB 32
#define TT 128
#define VV 16000
#define EE 512
#define ZZ 128
#define HH 1024
#define RR 64   // 2*B rows: [0,32)=free-running (stream 0), [32,64)=teacher (stream 1)
#define START_ID 1
#define NSPLIT 8      // split-K for gate GEMMs
#define NCHUNK 125    // logits blocks (n-chunks of 128)

// ---------------- device state ----------------
__device__ float g_h0[RR][HH];
__device__ float g_c0[RR][HH];
__device__ float g_h1[RR][HH];
__device__ float g_c1[RR][HH];
__device__ float g_part[NSPLIT][RR][4*HH];   // split-K partials for gate GEMMs
__device__ float g_logits[RR][VV];
__device__ float g_zb0[BB][4*HH];            // z @ Wx0[512:640] + b0 (step-invariant)
__device__ int   g_tok[RR];
// sampling partials (per row, per 128-col logits chunk)
__device__ float g_pm[RR][NCHUNK];           // chunk max
__device__ float g_ps[RR][NCHUNK];           // chunk sum of exp(L - chunk max)
__device__ float g_pb[RR][NCHUNK];           // chunk best score (L + gumbel)
__device__ int   g_pi[RR][NCHUNK];           // chunk best index

// ---------------- init ----------------
__global__ void init_kernel() {
    int i = blockIdx.x * blockDim.x + threadIdx.x;
    if (i < RR * HH) {
        ((float*)g_h0)[i] = 0.f;
        ((float*)g_c0)[i] = 0.f;
        ((float*)g_h1)[i] = 0.f;
        ((float*)g_c1)[i] = 0.f;
    }
    if (i < RR) g_tok[i] = START_ID;
}

// zb0[b][n] = sum_k z[b][k] * Wx0[512+k][n] + b0[n]   (once per launch)
__global__ void zb0_kernel(const float* __restrict__ z, const float* __restrict__ Wx0,
                           const float* __restrict__ b0) {
    int idx = blockIdx.x * blockDim.x + threadIdx.x;
    if (idx >= BB * 4 * HH) return;
    int b = idx >> 12, n = idx & 4095;
    float s = b0[n];
    for (int k = 0; k < ZZ; k++)
        s += z[b * ZZ + k] * Wx0[(size_t)(512 + k) * 4096 + n];
    g_zb0[b][n] = s;
}

// ---------------- threefry2x32 (exact JAX semantics) ----------------
__host__ __device__ __forceinline__ uint32_t rotl32(uint32_t v, int d) {
    return (v << d) | (v >> (32 - d));
}
__host__ __device__ __forceinline__ void threefry2x32(
    uint32_t k0, uint32_t k1, uint32_t x0, uint32_t x1, uint32_t* o0, uint32_t* o1)
{
    uint32_t ks2 = k0 ^ k1 ^ 0x1BD11BDAu;
    x0 += k0; x1 += k1;
#define TF_RND(R_) { x0 += x1; x1 = rotl32(x1, R_); x1 ^= x0; }
    TF_RND(13) TF_RND(15) TF_RND(26) TF_RND(6)
    x0 += k1;  x1 += ks2 + 1u;
    TF_RND(17) TF_RND(29) TF_RND(16) TF_RND(24)
    x0 += ks2; x1 += k0 + 2u;
    TF_RND(13) TF_RND(15) TF_RND(26) TF_RND(6)
    x0 += k0;  x1 += k1 + 3u;
    TF_RND(17) TF_RND(29) TF_RND(16) TF_RND(24)
    x0 += k1;  x1 += ks2 + 4u;
    TF_RND(13) TF_RND(15) TF_RND(26) TF_RND(6)
    x0 += ks2; x1 += k0 + 5u;
#undef TF_RND
    *o0 = x0; *o1 = x1;
}
static void h_fold(uint32_t k0, uint32_t k1, uint32_t d, uint32_t* o0, uint32_t* o1) {
    threefry2x32(k0, k1, 0u, d, o0, o1);
}
// JAX >= 0.4.30 partitionable threefry: counter = u64(idx) -> (0, idx), bits = o0^o1
__device__ __forceinline__ float jax_gumbel(uint32_t k0, uint32_t k1, uint32_t idx) {
    uint32_t o0, o1;
    threefry2x32(k0, k1, 0u, idx, &o0, &o1);
    uint32_t bits = o0 ^ o1;
    float f = __uint_as_float((bits >> 9) | 0x3f800000u) - 1.0f;
    float u = fmaxf(f, 1.17549435e-38f);
    return -logf(-logf(u));
}

// ---------------- gate GEMMs: M=64, BN=128, Kc=16, 256 thr, 8x4/thread, dbuf ----
// MODE 0: gates L0, K=1536 (8 slices of 192), A=[emb[tok]|h0], B=[Wx0(0:512);Wh0]
// MODE 1: gates L1, K=2048 (8 slices of 256), A=[h0|h1],       B=[Wx1;Wh1]
template<int MODE>
__device__ __forceinline__ void load_tile(
    int k0, int rA, int kkA, int n0, int tid,
    const float* __restrict__ emb,
    const float* __restrict__ W1,  const float* __restrict__ W2,
    const int* toks, float pa[4], float4& pb0, float4& pb1)
{
#pragma unroll
    for (int e = 0; e < 4; e++) {
        int k = k0 + kkA + e;
        float v;
        if (MODE == 0) {
            v = (k < 512) ? emb[(size_t)toks[rA] * EE + k] : g_h0[rA][k - 512];
        } else {
            v = (k < 1024) ? g_h0[rA][k] : g_h1[rA][k - 1024];
        }
        pa[e] = v;
    }
    {
        int kk = tid >> 4;
        int nn = (tid & 15) * 8;
        int k  = k0 + kk;
        const float* row;
        if (MODE == 0) row = (k < 512)  ? (W1 + (size_t)k * 4096)
                                        : (W2 + (size_t)(k - 512) * 4096);
        else           row = (k < 1024) ? (W1 + (size_t)k * 4096)
                                        : (W2 + (size_t)(k - 1024) * 4096);
        pb0 = *reinterpret_cast<const float4*>(row + n0 + nn);
        pb1 = *reinterpret_cast<const float4*>(row + n0 + nn + 4);
    }
}

template<int MODE>
__global__ __launch_bounds__(256) void gemm_kernel(
    const float* __restrict__ emb,
    const float* __restrict__ W1,  const float* __restrict__ W2)
{
    constexpr int KTOT = (MODE == 0) ? 1536 : 2048;
    constexpr int KS   = KTOT / NSPLIT;     // 192 / 256

    __shared__ float As[2][16][64];
    __shared__ float Bs[2][16][128];
    __shared__ int   toks[64];

    const int tid = threadIdx.x;
    const int n0  = blockIdx.x * 128;
    const int ks0 = blockIdx.y * KS;
    const int tx  = tid & 31;
    const int ty  = tid >> 5;
    const int rA  = tid >> 2;
    const int kkA = (tid & 3) * 4;

    if (MODE == 0) {
        if (tid < 64) toks[tid] = g_tok[tid];
        __syncthreads();
    }

    float acc[8][4];
#pragma unroll
    for (int i = 0; i < 8; i++)
#pragma unroll
        for (int j = 0; j < 4; j++) acc[i][j] = 0.f;

    float pa[4]; float4 pb0, pb1;

    load_tile<MODE>(ks0, rA, kkA, n0, tid, emb, W1, W2, toks, pa, pb0, pb1);
    {
        int kk = tid >> 4, nn = (tid & 15) * 8;
#pragma unroll
        for (int e = 0; e < 4; e++) As[0][kkA + e][rA] = pa[e];
        *reinterpret_cast<float4*>(&Bs[0][kk][nn])     = pb0;
        *reinterpret_cast<float4*>(&Bs[0][kk][nn + 4]) = pb1;
    }
    __syncthreads();

    int buf = 0;
    for (int k0 = ks0; k0 < ks0 + KS; k0 += 16) {
        const bool more = (k0 + 16) < (ks0 + KS);
        if (more)
            load_tile<MODE>(k0 + 16, rA, kkA, n0, tid, emb, W1, W2, toks, pa, pb0, pb1);

#pragma unroll
        for (int kk = 0; kk < 16; kk++) {
            float4 a0 = *reinterpret_cast<const float4*>(&As[buf][kk][ty * 8]);
            float4 a1 = *reinterpret_cast<const float4*>(&As[buf][kk][ty * 8 + 4]);
            float4 b4 = *reinterpret_cast<const float4*>(&Bs[buf][kk][tx * 4]);
            float a[8] = {a0.x, a0.y, a0.z, a0.w, a1.x, a1.y, a1.z, a1.w};
#pragma unroll
            for (int i = 0; i < 8; i++) {
                acc[i][0] += a[i] * b4.x;
                acc[i][1] += a[i] * b4.y;
                acc[i][2] += a[i] * b4.z;
                acc[i][3] += a[i] * b4.w;
            }
        }

        if (more) {
            int kk = tid >> 4, nn = (tid & 15) * 8;
            int nb = buf ^ 1;
#pragma unroll
            for (int e = 0; e < 4; e++) As[nb][kkA + e][rA] = pa[e];
            *reinterpret_cast<float4*>(&Bs[nb][kk][nn])     = pb0;
            *reinterpret_cast<float4*>(&Bs[nb][kk][nn + 4]) = pb1;
        }
        __syncthreads();
        buf ^= 1;
    }

    const int nc = n0 + tx * 4;
    float* P = &g_part[blockIdx.y][0][0];
#pragma unroll
    for (int i = 0; i < 8; i++) {
        int r = ty * 8 + i;
        float4 o;
        o.x = acc[i][0]; o.y = acc[i][1]; o.z = acc[i][2]; o.w = acc[i][3];
        *reinterpret_cast<float4*>(P + (size_t)r * 4096 + nc) = o;
    }
}

// ---------------- logits GEMM + fused sampling partials ---------------------
// grid = 125 blocks (n-chunks of 128), K=1024 full (no split).
// Epilogue: bias add, write g_logits, per-row chunk max / sumexp / argmax(L+g).
__global__ __launch_bounds__(256) void gemm2s_kernel(
    const float* __restrict__ Wout, const float* __restrict__ bout,
    uint32_t k0s0, uint32_t k1s0, uint32_t k0s1, uint32_t k1s1)
{
    __shared__ float As[2][16][64];
    __shared__ float Bs[2][16][128];

    const int tid = threadIdx.x;
    const int n0  = blockIdx.x * 128;
    const int tx  = tid & 31;
    const int ty  = tid >> 5;
    const int rA  = tid >> 2;
    const int kkA = (tid & 3) * 4;

    float acc[8][4];
#pragma unroll
    for (int i = 0; i < 8; i++)
#pragma unroll
        for (int j = 0; j < 4; j++) acc[i][j] = 0.f;

    float pa[4]; float4 pb0, pb1;

    // preload
    {
#pragma unroll
        for (int e = 0; e < 4; e++) pa[e] = g_h1[rA][kkA + e];
        int kk = tid >> 4, nn = (tid & 15) * 8;
        const float* row = Wout + (size_t)kk * VV;
        pb0 = *reinterpret_cast<const float4*>(row + n0 + nn);
        pb1 = *reinterpret_cast<const float4*>(row + n0 + nn + 4);
        for (int e = 0; e < 4; e++) As[0][kkA + e][rA] = pa[e];
        *reinterpret_cast<float4*>(&Bs[0][kk][nn])     = pb0;
        *reinterpret_cast<float4*>(&Bs[0][kk][nn + 4]) = pb1;
    }
    __syncthreads();

    int buf = 0;
    for (int k0 = 0; k0 < 1024; k0 += 16) {
        const bool more = (k0 + 16) < 1024;
        if (more) {
#pragma unroll
            for (int e = 0; e < 4; e++) pa[e] = g_h1[rA][k0 + 16 + kkA + e];
            int kk = tid >> 4, nn = (tid & 15) * 8;
            const float* row = Wout + (size_t)(k0 + 16 + kk) * VV;
            pb0 = *reinterpret_cast<const float4*>(row + n0 + nn);
            pb1 = *reinterpret_cast<const float4*>(row + n0 + nn + 4);
        }
#pragma unroll
        for (int kk = 0; kk < 16; kk++) {
            float4 a0 = *reinterpret_cast<const float4*>(&As[buf][kk][ty * 8]);
            float4 a1 = *reinterpret_cast<const float4*>(&As[buf][kk][ty * 8 + 4]);
            float4 b4 = *reinterpret_cast<const float4*>(&Bs[buf][kk][tx * 4]);
            float a[8] = {a0.x, a0.y, a0.z, a0.w, a1.x, a1.y, a1.z, a1.w};
#pragma unroll
            for (int i = 0; i < 8; i++) {
                acc[i][0] += a[i] * b4.x;
                acc[i][1] += a[i] * b4.y;
                acc[i][2] += a[i] * b4.z;
                acc[i][3] += a[i] * b4.w;
            }
        }
        if (more) {
            int kk = tid >> 4, nn = (tid & 15) * 8;
            int nb = buf ^ 1;
#pragma unroll
            for (int e = 0; e < 4; e++) As[nb][kkA + e][rA] = pa[e];
            *reinterpret_cast<float4*>(&Bs[nb][kk][nn])     = pb0;
            *reinterpret_cast<float4*>(&Bs[nb][kk][nn + 4]) = pb1;
        }
        __syncthreads();
        buf ^= 1;
    }

    // ---- epilogue: bias, store logits, per-row chunk stats -----------------
    const int nc = n0 + tx * 4;
    float4 bv = *reinterpret_cast<const float4*>(bout + nc);
    const int bx = blockIdx.x;

#pragma unroll 1
    for (int i = 0; i < 8; i++) {
        const int r = ty * 8 + i;
        float L[4];
        L[0] = acc[i][0] + bv.x;
        L[1] = acc[i][1] + bv.y;
        L[2] = acc[i][2] + bv.z;
        L[3] = acc[i][3] + bv.w;
        float4 o; o.x = L[0]; o.y = L[1]; o.z = L[2]; o.w = L[3];
        *reinterpret_cast<float4*>(&g_logits[r][nc]) = o;

        // chunk max over 128 cols (warp = fixed ty, lanes = tx)
        float lm = fmaxf(fmaxf(L[0], L[1]), fmaxf(L[2], L[3]));
#pragma unroll
        for (int off = 16; off > 0; off >>= 1)
            lm = fmaxf(lm, __shfl_xor_sync(0xFFFFFFFFu, lm, off));
        // chunk sumexp
        float ls = expf(L[0] - lm) + expf(L[1] - lm) + expf(L[2] - lm) + expf(L[3] - lm);
#pragma unroll
        for (int off = 16; off > 0; off >>= 1)
            ls += __shfl_xor_sync(0xFFFFFFFFu, ls, off);
        // gumbel argmax of L + g (argmax-invariant to row-constant shift)
        const int stream = (r < BB) ? 1 : 0;  // note: stream flag below
        const uint32_t k0 = (r < BB) ? k0s0 : k0s1;
        const uint32_t k1 = (r < BB) ? k1s0 : k1s1;
        (void)stream;
        const int b = r & 31;
        float best = -INFINITY; int bidx = VV;
#pragma unroll
        for (int q = 0; q < 4; q++) {
            int v = nc + q;
            float g = jax_gumbel(k0, k1, (uint32_t)(b * VV + v));
            float sc = L[q] + g;
            if (sc > best) { best = sc; bidx = v; }
        }
#pragma unroll
        for (int off = 16; off > 0; off >>= 1) {
            float ob = __shfl_xor_sync(0xFFFFFFFFu, best, off);
            int   oi = __shfl_xor_sync(0xFFFFFFFFu, bidx, off);
            if (ob > best || (ob == best && oi < bidx)) { best = ob; bidx = oi; }
        }
        if (tx == 0) {
            g_pm[r][bx] = lm;
            g_ps[r][bx] = ls;
            g_pb[r][bx] = best;
            g_pi[r][bx] = bidx;
        }
    }
}

// ---------------- LSTM cell: fused split-K reduce + bias/zb0 + cell ----------
__device__ __forceinline__ float sigf(float x) { return 1.f / (1.f + expf(-x)); }

__global__ __launch_bounds__(128) void cell_kernel(int layer, const float* __restrict__ bias) {
    int idx4 = blockIdx.x * 128 + threadIdx.x;
    if (idx4 >= RR * HH / 4) return;
    int r = idx4 >> 8;
    int j = (idx4 & 255) * 4;
    float* hA = layer ? &g_h1[0][0] : &g_h0[0][0];
    float* cA = layer ? &g_c1[0][0] : &g_c0[0][0];

    float4 gi, gf, gg, go;
    if (layer == 0) {
        const float* zb = &g_zb0[r & 31][0];
        gi = *reinterpret_cast<const float4*>(zb + j);
        gf = *reinterpret_cast<const float4*>(zb + j + HH);
        gg = *reinterpret_cast<const float4*>(zb + j + 2 * HH);
        go = *reinterpret_cast<const float4*>(zb + j + 3 * HH);
    } else {
        gi = *reinterpret_cast<const float4*>(bias + j);
        gf = *reinterpret_cast<const float4*>(bias + j + HH);
        gg = *reinterpret_cast<const float4*>(bias + j + 2 * HH);
        go = *reinterpret_cast<const float4*>(bias + j + 3 * HH);
    }
#pragma unroll
    for (int s = 0; s < NSPLIT; s++) {
        float4 a = *reinterpret_cast<const float4*>(&g_part[s][r][j]);
        float4 b = *reinterpret_cast<const float4*>(&g_part[s][r][j + HH]);
        float4 c = *reinterpret_cast<const float4*>(&g_part[s][r][j + 2 * HH]);
        float4 d = *reinterpret_cast<const float4*>(&g_part[s][r][j + 3 * HH]);
        gi.x += a.x; gi.y += a.y; gi.z += a.z; gi.w += a.w;
        gf.x += b.x; gf.y += b.y; gf.z += b.z; gf.w += b.w;
        gg.x += c.x; gg.y += c.y; gg.z += c.z; gg.w += c.w;
        go.x += d.x; go.y += d.y; go.z += d.z; go.w += d.w;
    }
    float4 cc = *reinterpret_cast<const float4*>(cA + (size_t)r * HH + j);
    float4 hh;
    cc.x = sigf(gf.x) * cc.x + sigf(gi.x) * tanhf(gg.x);
    cc.y = sigf(gf.y) * cc.y + sigf(gi.y) * tanhf(gg.y);
    cc.z = sigf(gf.z) * cc.z + sigf(gi.z) * tanhf(gg.z);
    cc.w = sigf(gf.w) * cc.w + sigf(gi.w) * tanhf(gg.w);
    hh.x = sigf(go.x) * tanhf(cc.x);
    hh.y = sigf(go.y) * tanhf(cc.y);
    hh.z = sigf(go.z) * tanhf(cc.z);
    hh.w = sigf(go.w) * tanhf(cc.w);
    *reinterpret_cast<float4*>(cA + (size_t)r * HH + j) = cc;
    *reinterpret_cast<float4*>(hA + (size_t)r * HH + j) = hh;
}

// ---------------- sample2: combine partials, write p, pick token -------------
// grid = RR*4 (4 vocab chunks of 4000 per row), 256 threads.
__global__ __launch_bounds__(256) void sample2_kernel(
    int t, const int* __restrict__ x, float* __restrict__ out)
{
    const int r   = blockIdx.x >> 2;
    const int c   = blockIdx.x & 3;
    const int tid = threadIdx.x;
    const int stream = (r < BB) ? 0 : 1;
    const int b   = r & 31;

    __shared__ float red[128];

    // combine 125 (m, s) partials -> mlse  (threads 0..127, padded)
    float m = (tid < NCHUNK) ? g_pm[r][tid] : -INFINITY;
    if (tid < 128) red[tid] = m;
    __syncthreads();
    for (int s = 64; s > 0; s >>= 1) {
        if (tid < s) red[tid] = fmaxf(red[tid], red[tid + s]);
        __syncthreads();
    }
    const float M = red[0];
    __syncthreads();
    float sv = (tid < NCHUNK) ? g_ps[r][tid] * expf(g_pm[r][tid] - M) : 0.f;
    if (tid < 128) red[tid] = sv;
    __syncthreads();
    for (int s = 64; s > 0; s >>= 1) {
        if (tid < s) red[tid] += red[tid + s];
        __syncthreads();
    }
    const float mlse = M + logf(red[0]);
    __syncthreads();

    // write p for this chunk
    const float4* L4 = reinterpret_cast<const float4*>(&g_logits[r][0]);
    const size_t p_off = stream ? ((size_t)4096 + (size_t)BB * TT * VV + 4096)
                                : (size_t)4096;
    const size_t pbase = p_off + ((size_t)b * TT + t) * VV;
    float4* O4 = reinterpret_cast<float4*>(out + pbase);
    const int v40 = c * 1000, v41 = v40 + 1000;
    for (int v4 = v40 + tid; v4 < v41; v4 += 256) {
        float4 a = L4[v4];
        float4 pw;
        pw.x = expf(a.x - mlse);
        pw.y = expf(a.y - mlse);
        pw.z = expf(a.z - mlse);
        pw.w = expf(a.w - mlse);
        O4[v4] = pw;
    }

    // chunk 0: combine argmax partials, write token
    if (c == 0) {
        __shared__ float rb[128];
        __shared__ int   ri[128];
        float best = -INFINITY; int bidx = VV;
        if (tid < NCHUNK) { best = g_pb[r][tid]; bidx = g_pi[r][tid]; }
        if (tid < 128) { rb[tid] = best; ri[tid] = bidx; }
        __syncthreads();
        for (int s = 64; s > 0; s >>= 1) {
            if (tid < s) {
                float o = rb[tid + s]; int oi = ri[tid + s];
                if (o > rb[tid] || (o == rb[tid] && oi < ri[tid])) {
                    rb[tid] = o; ri[tid] = oi;
                }
            }
            __syncthreads();
        }
        if (tid == 0) {
            int am = ri[0];
            size_t sbase = stream ? ((size_t)4096 + (size_t)BB * TT * VV) : (size_t)0;
            out[sbase + (size_t)b * TT + t] = (float)am;
            g_tok[r] = stream ? x[(size_t)b * TT + t] : am;
        }
    }
}

// ---------------- host driver ----------------
extern "C" void kernel_launch(void* const* d_in, const int* in_sizes, int n_in,
                              void* d_out, int out_size)
{
    const int*   x    = (const int*)  d_in[0];
    const float* z    = (const float*)d_in[1];
    const float* emb  = (const float*)d_in[2];
    const float* Wx0  = (const float*)d_in[3];
    const float* Wh0  = (const float*)d_in[4];
    const float* b0   = (const float*)d_in[5];
    const float* Wx1  = (const float*)d_in[6];
    const float* Wh1  = (const float*)d_in[7];
    const float* b1   = (const float*)d_in[8];
    const float* Wout = (const float*)d_in[9];
    const float* bout = (const float*)d_in[10];
    float* out = (float*)d_out;

    init_kernel<<<256, 256>>>();
    zb0_kernel<<<(BB * 4 * HH + 255) / 256, 256>>>(z, Wx0, b0);

    uint32_t s0a, s0b, s1a, s1b;
    h_fold(0u, 42u, 0u, &s0a, &s0b);
    h_fold(0u, 42u, 1u, &s1a, &s1b);

    for (int t = 0; t < TT; t++) {
        uint32_t k0s0, k1s0, k0s1, k1s1;
        h_fold(s0a, s0b, (uint32_t)t, &k0s0, &k1s0);
        h_fold(s1a, s1b, (uint32_t)t, &k0s1, &k1s1);

        gemm_kernel<0><<<dim3(32, NSPLIT), 256>>>(emb, Wx0, Wh0);
        cell_kernel<<<128, 128>>>(0, b0);
        gemm_kernel<1><<<dim3(32, NSPLIT), 256>>>(emb, Wx1, Wh1);
        cell_kernel<<<128, 128>>>(1, b1);
        gemm2s_kernel<<<NCHUNK, 256>>>(Wout, bout, k0s0, k1s0, k0s1, k1s1);
        sample2_kernel<<<RR * 4, 256>>>(t, x, out);
    }
}